// round 5
// baseline (speedup 1.0000x reference)
#include <cuda_runtime.h>
#include <cuda_bf16.h>
#include <math.h>
#include <stdint.h>

// Problem constants
#define BB 16
#define CC 8
#define LL 16384
#define RR 32

#define TM 512                 // t rows per CTA tile
#define NTILES 4096            // c-major: c=g>>9, b=(g>>5)&15, seg=g&31
#define NBLOCKS 152
#define NTHREADS 512           // 16 warps, each warp: m32 x n64

#define BSTRIDE 132            // uint32 words per B row (264 bf16, padded)

// SMEM offsets (bytes)
#define BH_OFF 0                         // B_hi: 64 rows * 132 words = 33792 B
#define BL_OFF 33792                     // B_lo
#define XW_OFF 67584                     // fp32 window: 776 floats
#define PEH_OFF (XW_OFF + 3104)          // even-pair hi: 384 words (+16 pad)
#define POH_OFF (PEH_OFF + 1600)
#define PEL_OFF (POH_OFF + 1600)
#define POL_OFF (PEL_OFF + 1600)
#define SG_OFF  (POL_OFF + 1600)
#define SMEM_BYTES (SG_OFF + 16)

// Gabor bank, bf16 hi/lo, padded: row n (0..63) = 2*pos + (0=re,1=im), tap w
__device__ __align__(16) __nv_bfloat16 g_bh[CC][64 * 2 * BSTRIDE];
__device__ __align__(16) __nv_bfloat16 g_bl[CC][64 * 2 * BSTRIDE];
__device__ int    g_pr[CC][32];      // sorted pos -> actual output r
__device__ uint2  g_ng[CC];          // packed ng[kc] (4 bits each), nested prefix counts
__device__ unsigned int g_counter;

__global__ void bank_kernel(const float* __restrict__ kV, const float* __restrict__ sV) {
    int idx = blockIdx.x * blockDim.x + threadIdx.x;
    if (idx == 0) g_counter = 0;
    if (idx >= 65536) return;
    int f = idx >> 8, w = idx & 255;
    int c = f >> 5, j = f & 31;
    float k = kV[f], s = sV[f];

    // sort rank within channel, sigma DESC (pos 0 = largest sigma), tie by j
    int pos = 0;
    for (int j2 = 0; j2 < 32; j2++) {
        float s2 = sV[c * 32 + j2];
        pos += (s2 > s) || (s2 == s && j2 < j);
    }

    float phase = ((float)(-2.0 * M_PI / 256.0) * k) * (float)w;
    double sp, cp;
    sincos((double)phase, &sp, &cp);
    float nm = (float)w - 128.0f;
    float s2v = s * s;
    float inv2s2 = 1.0f / (2.0f * s2v);
    float coef = 1.0f / sqrtf(2.0f * (float)M_PI * s2v);
    float gauss = coef * expf(-inv2s2 * nm * nm);
    float fre = (float)cp * gauss, fim = (float)sp * gauss;

    __nv_bfloat16 h = __float2bfloat16(fre);
    __nv_bfloat16 l = __float2bfloat16(fre - __bfloat162float(h));
    g_bh[c][(2 * pos) * 264 + w] = h;
    g_bl[c][(2 * pos) * 264 + w] = l;
    h = __float2bfloat16(fim);
    l = __float2bfloat16(fim - __bfloat162float(h));
    g_bh[c][(2 * pos + 1) * 264 + w] = h;
    g_bl[c][(2 * pos + 1) * 264 + w] = l;

    if (w == 0) g_pr[c][pos] = 31 - j;   // reference reverses R

    if (w == 0 && j == 0) {  // one thread per channel: nested ng table
        int hg[8];
        for (int gq = 0; gq < 8; gq++) {
            // sigma at sorted position 4*gq (max of the group, since desc)
            float sg = 4.0f;
            for (int j2 = 0; j2 < 32; j2++) {
                float sj2 = sV[c * 32 + j2];
                int p2 = 0;
                for (int j3 = 0; j3 < 32; j3++) {
                    float sj3 = sV[c * 32 + j3];
                    p2 += (sj3 > sj2) || (sj3 == sj2 && j3 < j2);
                }
                if (p2 == 4 * gq) sg = sj2;
            }
            float D = 4.5f * sg;
            int lo = (int)floorf((128.0f - D) * (1.0f / 16.0f));
            int hi = (int)floorf((128.0f + D) * (1.0f / 16.0f));
            if (lo < 0) lo = 0;
            if (hi > 15) hi = 15;
            int hh = (8 - lo) > (hi - 7) ? (8 - lo) : (hi - 7);
            if (hh < 1) hh = 1;
            if (hh > 8) hh = 8;
            hg[gq] = hh;
        }
        unsigned int n0 = 0, n1 = 0;
        for (int kc = 0; kc < 16; kc++) {
            int req = (kc < 8) ? (8 - kc) : (kc - 7);
            unsigned int cnt = 0;
            for (int gq = 0; gq < 8; gq++) cnt += (hg[gq] >= req);
            if (kc < 8) n0 |= cnt << (4 * kc);
            else        n1 |= cnt << (4 * (kc - 8));
        }
        g_ng[c] = make_uint2(n0, n1);
    }
}

__device__ __forceinline__ uint32_t pack2(__nv_bfloat16 a, __nv_bfloat16 b) {
    __nv_bfloat162 t(a, b);
    return *reinterpret_cast<uint32_t*>(&t);
}

__device__ __forceinline__ void mma16816(float* d,
                                         uint32_t a0, uint32_t a1, uint32_t a2, uint32_t a3,
                                         uint32_t b0, uint32_t b1) {
    asm volatile(
        "mma.sync.aligned.m16n8k16.row.col.f32.bf16.bf16.f32 "
        "{%0,%1,%2,%3}, {%4,%5,%6,%7}, {%8,%9}, {%0,%1,%2,%3};"
        : "+f"(d[0]), "+f"(d[1]), "+f"(d[2]), "+f"(d[3])
        : "r"(a0), "r"(a1), "r"(a2), "r"(a3), "r"(b0), "r"(b1));
}

__global__ void __launch_bounds__(NTHREADS, 1)
conv_kernel(const float* __restrict__ x, float* __restrict__ out) {
    extern __shared__ unsigned char smem[];
    float* xw = (float*)(smem + XW_OFF);
    uint32_t* PEHw = (uint32_t*)(smem + PEH_OFF);
    uint32_t* POHw = (uint32_t*)(smem + POH_OFF);
    uint32_t* PELw = (uint32_t*)(smem + PEL_OFF);
    uint32_t* POLw = (uint32_t*)(smem + POL_OFF);
    const uint32_t* BHw = (const uint32_t*)(smem + BH_OFF);
    const uint32_t* BLw = (const uint32_t*)(smem + BL_OFF);
    unsigned int* sgp = (unsigned int*)(smem + SG_OFF);

    int tid  = threadIdx.x;
    int wid  = tid >> 5;
    int lane = tid & 31;
    int lq   = lane >> 2;     // 0..7
    int lr   = lane & 3;      // 0..3
    int mwarp = wid * 32;
    int odd = lq & 1;
    int abase = (mwarp >> 1) + (lq >> 1) + lr;

    if (tid == 0) sgp[0] = atomicAdd(&g_counter, 1u);
    __syncthreads();
    unsigned int g = sgp[0];

    // prefetch first tile's x window: xw[j] = x[b, t0-128+j, c], j in [0,769)
    float v0 = 0, v1 = 0;
    {
        unsigned int gc = (g < NTILES) ? g : 0u;
        int c2 = gc >> 9, b2 = (gc >> 5) & 15, t02 = (int)(gc & 31) << 9;
        const float* xb = x + (size_t)b2 * LL * CC + c2;
        int l = t02 - 128 + tid;
        v0 = (l >= 0 && l < LL) ? xb[(size_t)l * CC] : 0.0f;
        if (tid < 257) v1 = (l + 512 < LL) ? xb[(size_t)(l + 512) * CC] : 0.0f;
    }

    int cur_c = -1;
    unsigned int ng0 = 0, ng1 = 0;
    int rcol[8];
    while (g < NTILES) {
        int c = g >> 9, b = (g >> 5) & 15, t0 = (int)(g & 31) << 9;

        __syncthreads();   // B1: previous tile's smem readers done

        if (c != cur_c) {  // stage B + per-channel tables
            const uint4* sH = (const uint4*)g_bh[c];
            const uint4* sL = (const uint4*)g_bl[c];
            uint4* dH = (uint4*)(smem + BH_OFF);
            uint4* dL = (uint4*)(smem + BL_OFF);
            for (int i = tid; i < 2112; i += NTHREADS) { dH[i] = sH[i]; dL[i] = sL[i]; }
            uint2 np = g_ng[c];
            ng0 = np.x; ng1 = np.y;
#pragma unroll
            for (int ns = 0; ns < 8; ns++) rcol[ns] = c * RR + g_pr[c][ns * 4 + lr];
            cur_c = c;
        }

        // stage fp32 window
        xw[tid] = v0;
        if (tid < 257) xw[512 + tid] = v1;
        if (tid == 0) sgp[1] = atomicAdd(&g_counter, 1u);
        __syncthreads();

        // build hi/lo even/odd bf16-pair arrays (384 entries)
        if (tid < 384) {
            float a0 = xw[2 * tid], a1 = xw[2 * tid + 1], a2 = xw[2 * tid + 2];
            __nv_bfloat16 h0 = __float2bfloat16(a0);
            __nv_bfloat16 l0 = __float2bfloat16(a0 - __bfloat162float(h0));
            __nv_bfloat16 h1 = __float2bfloat16(a1);
            __nv_bfloat16 l1 = __float2bfloat16(a1 - __bfloat162float(h1));
            __nv_bfloat16 h2 = __float2bfloat16(a2);
            __nv_bfloat16 l2 = __float2bfloat16(a2 - __bfloat162float(h2));
            PEHw[tid] = pack2(h0, h1); POHw[tid] = pack2(h1, h2);
            PELw[tid] = pack2(l0, l1); POLw[tid] = pack2(l1, l2);
        }
        __syncthreads();   // B2
        unsigned int gn = sgp[1];

        // prefetch next tile's x (hidden under the MMA mainloop)
        {
            unsigned int gc = (gn < NTILES) ? gn : 0u;
            int c2 = gc >> 9, b2 = (gc >> 5) & 15, t02 = (int)(gc & 31) << 9;
            const float* xb = x + (size_t)b2 * LL * CC + c2;
            int l = t02 - 128 + tid;
            v0 = (l >= 0 && l < LL) ? xb[(size_t)l * CC] : 0.0f;
            if (tid < 257) v1 = (l + 512 < LL) ? xb[(size_t)(l + 512) * CC] : 0.0f;
        }

        // ---- 3-pass hi/lo bf16 GEMM with nested sigma-truncated K ----
        float d[64];
#pragma unroll
        for (int i = 0; i < 64; i++) d[i] = 0.0f;

#pragma unroll 1
        for (int pass = 0; pass < 3; pass++) {
            const uint32_t* ap = (pass == 2) ? (odd ? POLw : PELw)
                                             : (odd ? POHw : PEHw);
            const uint32_t* bl = ((pass == 1) ? BLw : BHw) + lq * BSTRIDE + lr;
#pragma unroll
            for (int kc = 0; kc < 16; kc++) {
                unsigned int ng = ((kc < 8) ? (ng0 >> (4 * kc))
                                            : (ng1 >> (4 * (kc - 8)))) & 15u;
                if (ng == 0) continue;
                uint32_t w5[5];
#pragma unroll
                for (int u = 0; u < 5; u++) w5[u] = ap[abase + kc * 8 + 4 * u];
                if (ng == 8) {
                    uint32_t bq[16];
#pragma unroll
                    for (int ns = 0; ns < 8; ns++) {
                        bq[2 * ns]     = bl[ns * 8 * BSTRIDE + kc * 8];
                        bq[2 * ns + 1] = bl[ns * 8 * BSTRIDE + kc * 8 + 4];
                    }
#pragma unroll
                    for (int ms = 0; ms < 2; ms++)
#pragma unroll
                        for (int ns = 0; ns < 8; ns++)
                            mma16816(d + (ms * 8 + ns) * 4,
                                     w5[2 * ms], w5[2 * ms + 1], w5[2 * ms + 1], w5[2 * ms + 2],
                                     bq[2 * ns], bq[2 * ns + 1]);
                } else {
#pragma unroll 1
                    for (int gq = 0; gq < (int)ng; gq++) {
                        uint32_t b0 = bl[gq * 8 * BSTRIDE + kc * 8];
                        uint32_t b1 = bl[gq * 8 * BSTRIDE + kc * 8 + 4];
                        mma16816(d + gq * 4,      w5[0], w5[1], w5[1], w5[2], b0, b1);
                        mma16816(d + (8 + gq) * 4, w5[2], w5[3], w5[3], w5[4], b0, b1);
                    }
                }
            }
        }

        // ---- epilogue: power + permuted store ----
        size_t ob = ((size_t)(b * LL + t0 + mwarp + lq)) * (CC * RR);
#pragma unroll
        for (int ms = 0; ms < 2; ms++) {
#pragma unroll
            for (int ns = 0; ns < 8; ns++) {
                const float* dd = d + (ms * 8 + ns) * 4;
                float p0 = dd[0] * dd[0] + dd[1] * dd[1];
                float p1 = dd[2] * dd[2] + dd[3] * dd[3];
                out[ob + (size_t)(ms * 16) * (CC * RR) + rcol[ns]] = p0;
                out[ob + (size_t)(ms * 16 + 8) * (CC * RR) + rcol[ns]] = p1;
            }
        }

        g = gn;
    }
}

extern "C" void kernel_launch(void* const* d_in, const int* in_sizes, int n_in,
                              void* d_out, int out_size) {
    const float* x  = (const float*)d_in[0];
    const float* kV = (const float*)d_in[1];
    const float* sV = (const float*)d_in[2];
    float* out = (float*)d_out;

    cudaFuncSetAttribute(conv_kernel, cudaFuncAttributeMaxDynamicSharedMemorySize,
                         SMEM_BYTES);

    // 1) Gabor bank (sigma-sorted, bf16 hi/lo) + ng tables + queue reset
    bank_kernel<<<256, 256>>>(kV, sV);

    // 2) persistent implicit-GEMM wavelet transform (mma.sync bf16, truncated K)
    conv_kernel<<<NBLOCKS, NTHREADS, SMEM_BYTES>>>(x, out);
}

// round 6
// speedup vs baseline: 4.1182x; 4.1182x over previous
#include <cuda_runtime.h>
#include <cuda_bf16.h>
#include <math.h>
#include <stdint.h>

// Problem constants
#define BB 16
#define CC 8
#define LL 16384
#define RR 32

#define TM 512                 // t rows per CTA tile
#define NTILES 4096            // c-major: c=g>>9, b=(g>>5)&15, seg=g&31
#define NBLOCKS 152
#define NTHREADS 512           // 16 warps, each warp: m32 x n64

#define BSTRIDE 132            // uint32 words per B row (264 bf16, padded)

// SMEM offsets (bytes)
#define BH_OFF 0                         // B_hi: 64 rows * 132 words = 33792 B
#define BL_OFF 33792                     // B_lo
#define XW_OFF 67584                     // fp32 window: 776 floats
#define PEH_OFF (XW_OFF + 3104)          // even-pair hi: 384 words (+16 pad)
#define POH_OFF (PEH_OFF + 1600)
#define PEL_OFF (POH_OFF + 1600)
#define POL_OFF (PEL_OFF + 1600)
#define SG_OFF  (POL_OFF + 1600)
#define SMEM_BYTES (SG_OFF + 16)

// Gabor bank, bf16 hi/lo, padded: row n (0..63) = 2*pos + (0=re,1=im), tap w
__device__ __align__(16) __nv_bfloat16 g_bh[CC][64 * 2 * BSTRIDE];
__device__ __align__(16) __nv_bfloat16 g_bl[CC][64 * 2 * BSTRIDE];
__device__ int    g_pr[CC][32];      // sorted pos -> actual output r
__device__ uint2  g_ng[CC];          // packed ng[kc] (4 bits each), nested prefix counts
__device__ unsigned int g_counter;

__global__ void bank_kernel(const float* __restrict__ kV, const float* __restrict__ sV) {
    int idx = blockIdx.x * blockDim.x + threadIdx.x;
    if (idx == 0) g_counter = 0;
    if (idx >= 65536) return;
    int f = idx >> 8, w = idx & 255;
    int c = f >> 5, j = f & 31;
    float k = kV[f], s = sV[f];

    // sort rank within channel, sigma DESC (pos 0 = largest sigma), tie by j
    int pos = 0;
    for (int j2 = 0; j2 < 32; j2++) {
        float s2 = sV[c * 32 + j2];
        pos += (s2 > s) || (s2 == s && j2 < j);
    }

    float phase = ((float)(-2.0 * M_PI / 256.0) * k) * (float)w;
    double sp, cp;
    sincos((double)phase, &sp, &cp);
    float nm = (float)w - 128.0f;
    float s2v = s * s;
    float inv2s2 = 1.0f / (2.0f * s2v);
    float coef = 1.0f / sqrtf(2.0f * (float)M_PI * s2v);
    float gauss = coef * expf(-inv2s2 * nm * nm);
    float fre = (float)cp * gauss, fim = (float)sp * gauss;

    __nv_bfloat16 h = __float2bfloat16(fre);
    __nv_bfloat16 l = __float2bfloat16(fre - __bfloat162float(h));
    g_bh[c][(2 * pos) * 264 + w] = h;
    g_bl[c][(2 * pos) * 264 + w] = l;
    h = __float2bfloat16(fim);
    l = __float2bfloat16(fim - __bfloat162float(h));
    g_bh[c][(2 * pos + 1) * 264 + w] = h;
    g_bl[c][(2 * pos + 1) * 264 + w] = l;

    if (w == 0) g_pr[c][pos] = 31 - j;   // reference reverses R

    if (w == 0 && j == 0) {  // one thread per channel: nested ng table
        int hg[8];
        for (int gq = 0; gq < 8; gq++) {
            // sigma at sorted position 4*gq (max of the group, since desc)
            float sg = 4.0f;
            for (int j2 = 0; j2 < 32; j2++) {
                float sj2 = sV[c * 32 + j2];
                int p2 = 0;
                for (int j3 = 0; j3 < 32; j3++) {
                    float sj3 = sV[c * 32 + j3];
                    p2 += (sj3 > sj2) || (sj3 == sj2 && j3 < j2);
                }
                if (p2 == 4 * gq) sg = sj2;
            }
            float D = 4.5f * sg;
            int lo = (int)floorf((128.0f - D) * (1.0f / 16.0f));
            int hi = (int)floorf((128.0f + D) * (1.0f / 16.0f));
            if (lo < 0) lo = 0;
            if (hi > 15) hi = 15;
            int hh = (8 - lo) > (hi - 7) ? (8 - lo) : (hi - 7);
            if (hh < 1) hh = 1;
            if (hh > 8) hh = 8;
            hg[gq] = hh;
        }
        unsigned int n0 = 0, n1 = 0;
        for (int kc = 0; kc < 16; kc++) {
            int req = (kc < 8) ? (8 - kc) : (kc - 7);
            unsigned int cnt = 0;
            for (int gq = 0; gq < 8; gq++) cnt += (hg[gq] >= req);
            if (kc < 8) n0 |= cnt << (4 * kc);
            else        n1 |= cnt << (4 * (kc - 8));
        }
        g_ng[c] = make_uint2(n0, n1);
    }
}

__device__ __forceinline__ uint32_t pack2(__nv_bfloat16 a, __nv_bfloat16 b) {
    __nv_bfloat162 t(a, b);
    return *reinterpret_cast<uint32_t*>(&t);
}

__device__ __forceinline__ void mma16816(float* d,
                                         uint32_t a0, uint32_t a1, uint32_t a2, uint32_t a3,
                                         uint32_t b0, uint32_t b1) {
    asm volatile(
        "mma.sync.aligned.m16n8k16.row.col.f32.bf16.bf16.f32 "
        "{%0,%1,%2,%3}, {%4,%5,%6,%7}, {%8,%9}, {%0,%1,%2,%3};"
        : "+f"(d[0]), "+f"(d[1]), "+f"(d[2]), "+f"(d[3])
        : "r"(a0), "r"(a1), "r"(a2), "r"(a3), "r"(b0), "r"(b1));
}

__global__ void __launch_bounds__(NTHREADS, 1)
conv_kernel(const float* __restrict__ x, float* __restrict__ out) {
    extern __shared__ unsigned char smem[];
    float* xw = (float*)(smem + XW_OFF);
    uint32_t* PEHw = (uint32_t*)(smem + PEH_OFF);
    uint32_t* POHw = (uint32_t*)(smem + POH_OFF);
    uint32_t* PELw = (uint32_t*)(smem + PEL_OFF);
    uint32_t* POLw = (uint32_t*)(smem + POL_OFF);
    const uint32_t* BHw = (const uint32_t*)(smem + BH_OFF);
    const uint32_t* BLw = (const uint32_t*)(smem + BL_OFF);
    unsigned int* sgp = (unsigned int*)(smem + SG_OFF);

    int tid  = threadIdx.x;
    int wid  = tid >> 5;
    int lane = tid & 31;
    int lq   = lane >> 2;     // 0..7
    int lr   = lane & 3;      // 0..3
    int mwarp = wid * 32;
    int odd = lq & 1;
    int abase = (mwarp >> 1) + (lq >> 1) + lr;

    if (tid == 0) sgp[0] = atomicAdd(&g_counter, 1u);
    __syncthreads();
    unsigned int g = sgp[0];

    // prefetch first tile's x window: xw[j] = x[b, t0-128+j, c], j in [0,769)
    float v0 = 0, v1 = 0;
    {
        unsigned int gc = (g < NTILES) ? g : 0u;
        int c2 = gc >> 9, b2 = (gc >> 5) & 15, t02 = (int)(gc & 31) << 9;
        const float* xb = x + (size_t)b2 * LL * CC + c2;
        int l = t02 - 128 + tid;
        v0 = (l >= 0 && l < LL) ? xb[(size_t)l * CC] : 0.0f;
        if (tid < 257) v1 = (l + 512 < LL) ? xb[(size_t)(l + 512) * CC] : 0.0f;
    }

    int cur_c = -1;
    unsigned int ng0 = 0, ng1 = 0;
    int rcol[8];
    while (g < NTILES) {
        int c = g >> 9, b = (g >> 5) & 15, t0 = (int)(g & 31) << 9;

        __syncthreads();   // B1: previous tile's smem readers done

        if (c != cur_c) {  // stage B + per-channel tables
            const uint4* sH = (const uint4*)g_bh[c];
            const uint4* sL = (const uint4*)g_bl[c];
            uint4* dH = (uint4*)(smem + BH_OFF);
            uint4* dL = (uint4*)(smem + BL_OFF);
            for (int i = tid; i < 2112; i += NTHREADS) { dH[i] = sH[i]; dL[i] = sL[i]; }
            uint2 np = g_ng[c];
            ng0 = np.x; ng1 = np.y;
#pragma unroll
            for (int ns = 0; ns < 8; ns++) rcol[ns] = c * RR + g_pr[c][ns * 4 + lr];
            cur_c = c;
        }

        // stage fp32 window
        xw[tid] = v0;
        if (tid < 257) xw[512 + tid] = v1;
        if (tid == 0) sgp[1] = atomicAdd(&g_counter, 1u);
        __syncthreads();

        // build hi/lo even/odd bf16-pair arrays (384 entries)
        if (tid < 384) {
            float a0 = xw[2 * tid], a1 = xw[2 * tid + 1], a2 = xw[2 * tid + 2];
            __nv_bfloat16 h0 = __float2bfloat16(a0);
            __nv_bfloat16 l0 = __float2bfloat16(a0 - __bfloat162float(h0));
            __nv_bfloat16 h1 = __float2bfloat16(a1);
            __nv_bfloat16 l1 = __float2bfloat16(a1 - __bfloat162float(h1));
            __nv_bfloat16 h2 = __float2bfloat16(a2);
            __nv_bfloat16 l2 = __float2bfloat16(a2 - __bfloat162float(h2));
            PEHw[tid] = pack2(h0, h1); POHw[tid] = pack2(h1, h2);
            PELw[tid] = pack2(l0, l1); POLw[tid] = pack2(l1, l2);
        }
        __syncthreads();   // B2
        unsigned int gn = sgp[1];

        // prefetch next tile's x (hidden under the MMA mainloop)
        {
            unsigned int gc = (gn < NTILES) ? gn : 0u;
            int c2 = gc >> 9, b2 = (gc >> 5) & 15, t02 = (int)(gc & 31) << 9;
            const float* xb = x + (size_t)b2 * LL * CC + c2;
            int l = t02 - 128 + tid;
            v0 = (l >= 0 && l < LL) ? xb[(size_t)l * CC] : 0.0f;
            if (tid < 257) v1 = (l + 512 < LL) ? xb[(size_t)(l + 512) * CC] : 0.0f;
        }

        // ---- 3-pass hi/lo bf16 GEMM with nested sigma-truncated K ----
        // All accumulator indices are compile-time; truncation via uniform
        // (block-wide) guards so d[] stays in registers.
        float d[64];
#pragma unroll
        for (int i = 0; i < 64; i++) d[i] = 0.0f;

#pragma unroll 1
        for (int pass = 0; pass < 3; pass++) {
            const uint32_t* ap = (pass == 2) ? (odd ? POLw : PELw)
                                             : (odd ? POHw : PEHw);
            const uint32_t* bl = ((pass == 1) ? BLw : BHw) + lq * BSTRIDE + lr;
#pragma unroll
            for (int kc = 0; kc < 16; kc++) {
                int ng = (int)(((kc < 8) ? (ng0 >> (4 * kc))
                                         : (ng1 >> (4 * (kc - 8)))) & 15u);
                if (ng == 0) continue;
                uint32_t w5[5];
#pragma unroll
                for (int u = 0; u < 5; u++) w5[u] = ap[abase + kc * 8 + 4 * u];
#pragma unroll
                for (int gq = 0; gq < 8; gq++) {
                    if (gq < ng) {   // uniform across block -> no divergence
                        uint32_t b0 = bl[gq * 8 * BSTRIDE + kc * 8];
                        uint32_t b1 = bl[gq * 8 * BSTRIDE + kc * 8 + 4];
                        mma16816(d + gq * 4,       w5[0], w5[1], w5[1], w5[2], b0, b1);
                        mma16816(d + 32 + gq * 4,  w5[2], w5[3], w5[3], w5[4], b0, b1);
                    }
                }
            }
        }

        // ---- epilogue: power + permuted store ----
        size_t ob = ((size_t)(b * LL + t0 + mwarp + lq)) * (CC * RR);
#pragma unroll
        for (int ms = 0; ms < 2; ms++) {
#pragma unroll
            for (int ns = 0; ns < 8; ns++) {
                const float* dd = d + ms * 32 + ns * 4;
                float p0 = dd[0] * dd[0] + dd[1] * dd[1];
                float p1 = dd[2] * dd[2] + dd[3] * dd[3];
                out[ob + (size_t)(ms * 16) * (CC * RR) + rcol[ns]] = p0;
                out[ob + (size_t)(ms * 16 + 8) * (CC * RR) + rcol[ns]] = p1;
            }
        }

        g = gn;
    }
}

extern "C" void kernel_launch(void* const* d_in, const int* in_sizes, int n_in,
                              void* d_out, int out_size) {
    const float* x  = (const float*)d_in[0];
    const float* kV = (const float*)d_in[1];
    const float* sV = (const float*)d_in[2];
    float* out = (float*)d_out;

    cudaFuncSetAttribute(conv_kernel, cudaFuncAttributeMaxDynamicSharedMemorySize,
                         SMEM_BYTES);

    // 1) Gabor bank (sigma-sorted, bf16 hi/lo) + ng tables + queue reset
    bank_kernel<<<256, 256>>>(kV, sV);

    // 2) persistent implicit-GEMM wavelet transform (mma.sync bf16, truncated K)
    conv_kernel<<<NBLOCKS, NTHREADS, SMEM_BYTES>>>(x, out);
}